// round 17
// baseline (speedup 1.0000x reference)
#include <cuda_runtime.h>
#include <cuda_fp16.h>
#include <math.h>
#include <stdint.h>

// ---------------------------------------------------------------------------
// MTCNN P-Net forward. fp16 tensor-core path, PAIRED activation layout.
// conv1: scalar FFMA2 (norm folded), div-free staging -> g_p1h.
// conv2+conv3 FUSED: one block computes conv2 (144px x 6 rows) into SMEM,
// sync, then conv3 (128px x 4 rows) + 1x1 heads + softmax from SMEM.
// ---------------------------------------------------------------------------

#define B       16
#define H0      720
#define HP      359
#define H2      357
#define H3      355
#define P3      (H3*H3)

typedef unsigned long long ull;

__device__ __forceinline__ ull pack2(float a, float b) {
    ull r;
    asm("mov.b64 %0, {%1,%2};" : "=l"(r)
        : "r"(__float_as_uint(a)), "r"(__float_as_uint(b)));
    return r;
}
__device__ __forceinline__ void unpack2(ull v, float& a, float& b) {
    unsigned lo, hi;
    asm("mov.b64 {%0,%1}, %2;" : "=r"(lo), "=r"(hi) : "l"(v));
    a = __uint_as_float(lo); b = __uint_as_float(hi);
}
__device__ __forceinline__ void fma2(ull& d, ull a, ull b) {
    asm("fma.rn.f32x2 %0, %1, %2, %3;" : "=l"(d) : "l"(a), "l"(b), "l"(d));
}

// conv1 output, PAIRED layout: pixel*8 + q4*2 + {0 = slot q4, 1 = slot q4+4}
__device__ uint32_t g_p1h[(size_t)B*HP*HP*8];

// ======================= mma.sync helpers (fp16) ===========================
__device__ __forceinline__ void mma16816h(float* d, const uint32_t* a,
                                          uint32_t b0, uint32_t b1) {
    asm volatile(
        "mma.sync.aligned.m16n8k16.row.col.f32.f16.f16.f32 "
        "{%0,%1,%2,%3}, {%4,%5,%6,%7}, {%8,%9}, {%0,%1,%2,%3};"
        : "+f"(d[0]), "+f"(d[1]), "+f"(d[2]), "+f"(d[3])
        : "r"(a[0]), "r"(a[1]), "r"(a[2]), "r"(a[3]), "r"(b0), "r"(b1));
}

// load one input-row batch from gmem: 6 uint2 (kx 0..2 x {p0,p1})
__device__ __forceinline__ void load_ky1(uint2 (&L)[6], const uint32_t* rp,
                                         int p0c, int p1c) {
    #pragma unroll
    for (int kx = 0; kx < 3; kx++) {
        L[kx*2+0] = *(const uint2*)&rp[(size_t)(p0c + kx)*8];
        L[kx*2+1] = *(const uint2*)&rp[(size_t)(p1c + kx)*8];
    }
}

// ---------------------------------------------------------------------------
// Kernel 1: conv1(3x3,3->10) + PReLU + maxpool2 -> fp16 paired ch-last
// ---------------------------------------------------------------------------
__device__ __forceinline__ void conv1_taps(
    ull (&acc)[5][4], const ull sWp[5][3][9], int ci, int ky,
    const ull* top, const ull* bot)
{
    #pragma unroll
    for (int kx = 0; kx < 3; kx++) {
        #pragma unroll
        for (int cp = 0; cp < 5; cp++) {
            ull wp = sWp[cp][ci][ky*3+kx];
            fma2(acc[cp][0], wp, top[kx]);
            fma2(acc[cp][1], wp, top[kx+1]);
            fma2(acc[cp][2], wp, bot[kx]);
            fma2(acc[cp][3], wp, bot[kx+1]);
        }
    }
}

__global__ __launch_bounds__(128, 8) void k_conv1_pool(
    const float* __restrict__ x, const float* __restrict__ w1,
    const float* __restrict__ b1, const float* __restrict__ a1)
{
    __shared__ ull   sWp[5][3][9];
    __shared__ ull   sIn[3][10][66];
    __shared__ float sB[10], sA[10];

    const int b   = blockIdx.z;
    const int px0 = blockIdx.x * 32;
    const int py0 = blockIdx.y * 4;
    const int tid = threadIdx.y * 32 + threadIdx.x;
    const float SC = 0.0078125f;

    for (int i = tid; i < 135; i += 128) {
        int cp = i / 27, ci = (i % 27) / 9, k = i % 9;
        sWp[cp][ci][k] = pack2(w1[(2*cp)*27 + ci*9 + k] * SC,
                               w1[(2*cp+1)*27 + ci*9 + k] * SC);
    }
    if (tid < 10) {
        float s = 0.f;
        #pragma unroll
        for (int k = 0; k < 27; k++) s += w1[tid*27 + k];
        sB[tid] = b1[tid] - 127.5f * SC * s;
        sA[tid] = a1[tid];
    }

    const int row0 = 2*py0, col0 = 2*px0;
    {
        const int c  = tid & 63;
        const int r2 = tid >> 6;
        const int gc = col0 + c;
        const bool cok = (gc < H0);
        #pragma unroll
        for (int ci = 0; ci < 3; ci++) {
            #pragma unroll
            for (int r = 0; r < 5; r++) {
                const int rr = 2*r + r2;
                const int gr = row0 + rr;
                float v = 0.f;
                if (cok && gr < H0) v = x[((b*3+ci)*H0 + gr)*H0 + gc];
                sIn[ci][rr][c] = pack2(v, v);
            }
        }
        if (tid < 60) {
            int ci = tid / 20, rem = tid % 20;
            int rr = rem >> 1, c2 = 64 + (rem & 1);
            int gr = row0 + rr, gc2 = col0 + c2;
            float v = 0.f;
            if (gr < H0 && gc2 < H0) v = x[((b*3+ci)*H0 + gr)*H0 + gc2];
            sIn[ci][rr][c2] = pack2(v, v);
        }
    }
    __syncthreads();

    const int px = px0 + threadIdx.x;
    const int py = py0 + threadIdx.y;
    if (px >= HP || py >= HP) return;

    ull acc[5][4];
    #pragma unroll
    for (int cp = 0; cp < 5; cp++) {
        ull bb = pack2(sB[2*cp], sB[2*cp+1]);
        acc[cp][0]=bb; acc[cp][1]=bb; acc[cp][2]=bb; acc[cp][3]=bb;
    }

    const int lr = 2*threadIdx.y, lc = 2*threadIdx.x;
    #pragma unroll
    for (int ci = 0; ci < 3; ci++) {
        ull qa[4], qb[4];
        #pragma unroll
        for (int j = 0; j < 4; j++) qa[j] = sIn[ci][lr  ][lc+j];
        #pragma unroll
        for (int j = 0; j < 4; j++) qb[j] = sIn[ci][lr+1][lc+j];
        conv1_taps(acc, sWp, ci, 0, qa, qb);
        #pragma unroll
        for (int j = 0; j < 4; j++) qa[j] = sIn[ci][lr+2][lc+j];
        conv1_taps(acc, sWp, ci, 1, qb, qa);
        #pragma unroll
        for (int j = 0; j < 4; j++) qb[j] = sIn[ci][lr+3][lc+j];
        conv1_taps(acc, sWp, ci, 2, qa, qb);
    }

    float v[16];
    #pragma unroll
    for (int cp = 0; cp < 5; cp++) {
        float a0 = sA[2*cp], a1v = sA[2*cp+1];
        float m0 = -INFINITY, m1 = -INFINITY;
        #pragma unroll
        for (int k = 0; k < 4; k++) {
            float v0, v1; unpack2(acc[cp][k], v0, v1);
            v0 = (v0 >= 0.f) ? v0 : a0*v0;
            v1 = (v1 >= 0.f) ? v1 : a1v*v1;
            m0 = fmaxf(m0, v0); m1 = fmaxf(m1, v1);
        }
        v[2*cp] = m0; v[2*cp+1] = m1;
    }
    #pragma unroll
    for (int c = 10; c < 16; c++) v[c] = 0.f;

    uint32_t h[8];
    #pragma unroll
    for (int q4 = 0; q4 < 4; q4++) {
        __half2 lo = __floats2half2_rn(v[2*q4],     v[2*q4+1]);
        __half2 hi = __floats2half2_rn(v[2*q4 + 8], v[2*q4+9]);
        h[q4*2]   = *(uint32_t*)&lo;
        h[q4*2+1] = *(uint32_t*)&hi;
    }

    uint4* dst = (uint4*)&g_p1h[((size_t)(b*HP + py)*HP + px)*8];
    dst[0] = make_uint4(h[0], h[1], h[2], h[3]);
    dst[1] = make_uint4(h[4], h[5], h[6], h[7]);
}

// ---------------------------------------------------------------------------
// Kernel 2: FUSED conv2 + conv3 + heads.
// 288 threads = 9 warps. Phase A: conv2 for 144px x 6 rows into SMEM (paired).
// Phase B: 8 warps do conv3 128px x 4 rows + heads + softmax from SMEM.
// ---------------------------------------------------------------------------
__global__ __launch_bounds__(288, 2) void k_conv23_fused(
    const float* __restrict__ w2, const float* __restrict__ b2,
    const float* __restrict__ a2,
    const float* __restrict__ w3, const float* __restrict__ b3,
    const float* __restrict__ a3,
    const float* __restrict__ w41, const float* __restrict__ b41,
    const float* __restrict__ w42, const float* __restrict__ b42,
    float* __restrict__ out)
{
    __shared__ uint32_t sC2[6*144*8];     // conv2 tile, paired layout (27648B)
    __shared__ uint2 sW2[9*2*32];
    __shared__ uint2 sW3[9*4*32];
    __shared__ float sBA2[32];
    __shared__ float sBA3[64];
    __shared__ float sHW[6][32];
    __shared__ float sHB[6];

    const int b    = blockIdx.z;
    const int ox0  = blockIdx.x * 128;    // conv3 x base == conv2 x base
    const int oy0  = blockIdx.y * 4;      // conv3 y base == conv2 y base
    const int tid  = threadIdx.x;
    const int wid  = tid >> 5;
    const int lane = tid & 31;

    // ---- stage conv2 weight frags
    for (int f = tid; f < 9*2*32; f += 288) {
        int kc = f >> 6, cg = (f >> 5) & 1, ln = f & 31;
        int g = ln >> 2, ci0 = (ln & 3) * 2;
        int co = cg*8 + g;
        int ky = kc / 3, kx = kc % 3;
        float v0 = (ci0   < 10) ? w2[((co*10 + ci0  )*3 + ky)*3 + kx] : 0.f;
        float v1 = (ci0+1 < 10) ? w2[((co*10 + ci0+1)*3 + ky)*3 + kx] : 0.f;
        float v2 = (ci0+8 < 10) ? w2[((co*10 + ci0+8)*3 + ky)*3 + kx] : 0.f;
        float v3 = (ci0+9 < 10) ? w2[((co*10 + ci0+9)*3 + ky)*3 + kx] : 0.f;
        __half2 h0 = __floats2half2_rn(v0, v1);
        __half2 h1 = __floats2half2_rn(v2, v3);
        sW2[f] = make_uint2(*(uint32_t*)&h0, *(uint32_t*)&h1);
    }
    // ---- stage conv3 weight frags
    for (int f = tid; f < 9*4*32; f += 288) {
        int kc = f >> 7, cg = (f >> 5) & 3, ln = f & 31;
        int g = ln >> 2, ci0 = (ln & 3) * 2;
        int co = cg*8 + g;
        int ky = kc / 3, kx = kc % 3;
        __half2 h0 = __floats2half2_rn(w3[((co*16 + ci0  )*3 + ky)*3 + kx],
                                       w3[((co*16 + ci0+1)*3 + ky)*3 + kx]);
        __half2 h1 = __floats2half2_rn(w3[((co*16 + ci0+8)*3 + ky)*3 + kx],
                                       w3[((co*16 + ci0+9)*3 + ky)*3 + kx]);
        sW3[f] = make_uint2(*(uint32_t*)&h0, *(uint32_t*)&h1);
    }
    if (tid < 16) { sBA2[tid] = b2[tid]; sBA2[16+tid] = a2[tid]; }
    if (tid >= 32 && tid < 64) { sBA3[tid-32] = b3[tid-32]; sBA3[32+tid-32] = a3[tid-32]; }
    if (tid >= 64 && tid < 128) sHW[(tid-64)/32][(tid-64)%32] = w41[tid-64];
    if (tid >= 128 && tid < 256) sHW[2 + (tid-128)/32][(tid-128)%32] = w42[tid-128];
    if (tid >= 256 && tid < 258) sHB[tid-256] = b41[tid-256];
    if (tid >= 258 && tid < 262) sHB[tid-256] = b42[tid-258];
    __syncthreads();

    const int q4 = lane & 3;
    const int g  = lane >> 2;

    // ======================= Phase A: conv2 -> SMEM ========================
    {
        const int p0l = wid*16 + g;              // local conv2 x (0..143)
        const int p1l = p0l + 8;
        const int p0c = min(ox0 + p0l, HP - 3);  // valid conv2 x <= HP-3
        const int p1c = min(ox0 + p1l, HP - 3);

        float acc[6][2][4];
        #pragma unroll
        for (int t = 0; t < 6; t++)
            #pragma unroll
            for (int cg = 0; cg < 2; cg++)
                #pragma unroll
                for (int j = 0; j < 4; j++) acc[t][cg][j] = 0.f;

        uint2 cur[6], nxt[6];
        load_ky1(cur, &g_p1h[((size_t)(b*HP + min(oy0, HP-1)) * HP) * 8 + q4*2],
                 p0c, p1c);

        #pragma unroll
        for (int i = 0; i < 8; i++) {
            if (i < 7)
                load_ky1(nxt,
                    &g_p1h[((size_t)(b*HP + min(oy0+i+1, HP-1)) * HP) * 8 + q4*2],
                    p0c, p1c);
            #pragma unroll
            for (int kx = 0; kx < 3; kx++) {
                uint32_t ah[4] = {cur[kx*2+0].x, cur[kx*2+1].x,
                                  cur[kx*2+0].y, cur[kx*2+1].y};
                #pragma unroll
                for (int t = 0; t < 6; t++) {
                    if (t > i || t < i - 2) continue;
                    const int kc = 3*(i - t) + kx;
                    uint2 f0 = sW2[(kc*2 + 0)*32 + lane];
                    uint2 f1 = sW2[(kc*2 + 1)*32 + lane];
                    mma16816h(acc[t][0], ah, f0.x, f0.y);
                    mma16816h(acc[t][1], ah, f1.x, f1.y);
                }
            }
            #pragma unroll
            for (int j = 0; j < 6; j++) cur[j] = nxt[j];
        }

        const int ci0 = q4 * 2;
        #pragma unroll
        for (int t = 0; t < 6; t++) {
            #pragma unroll
            for (int cg = 0; cg < 2; cg++) {
                const int co = cg*8 + ci0;
                const float bb0 = sBA2[co], bb1 = sBA2[co+1];
                const float aa0 = sBA2[16+co], aa1 = sBA2[16+co+1];
                float t0 = acc[t][cg][0] + bb0, t1 = acc[t][cg][1] + bb1;
                float t2 = acc[t][cg][2] + bb0, t3 = acc[t][cg][3] + bb1;
                float o00 = (t0 >= 0.f) ? t0 : aa0*t0;
                float o01 = (t1 >= 0.f) ? t1 : aa1*t1;
                float o10 = (t2 >= 0.f) ? t2 : aa0*t2;
                float o11 = (t3 >= 0.f) ? t3 : aa1*t3;
                __half2 s0 = __floats2half2_rn(o00, o01);
                __half2 s1 = __floats2half2_rn(o10, o11);
                sC2[(t*144 + p0l)*8 + q4*2 + cg] = *(uint32_t*)&s0;
                sC2[(t*144 + p1l)*8 + q4*2 + cg] = *(uint32_t*)&s1;
            }
        }
    }
    __syncthreads();

    // ======================= Phase B: conv3 + heads ========================
    if (wid < 8) {
        const int p0l = wid*16 + g;        // local conv3 x (0..127)
        const int p1l = p0l + 8;
        const int ci0 = q4 * 2;
        const int q   = q4;

        float* regp  = out;
        float* probp = out + (size_t)B * 4 * P3;

        float acc[4][4][4];
        #pragma unroll
        for (int r = 0; r < 4; r++)
            #pragma unroll
            for (int cg = 0; cg < 4; cg++)
                #pragma unroll
                for (int j = 0; j < 4; j++) acc[r][cg][j] = 0.f;

        #pragma unroll
        for (int i = 0; i < 6; i++) {
            uint2 L[6];
            #pragma unroll
            for (int kx = 0; kx < 3; kx++) {
                L[kx*2+0] = *(const uint2*)&sC2[(i*144 + p0l + kx)*8 + q4*2];
                L[kx*2+1] = *(const uint2*)&sC2[(i*144 + p1l + kx)*8 + q4*2];
            }
            #pragma unroll
            for (int kx = 0; kx < 3; kx++) {
                uint32_t ah[4] = {L[kx*2+0].x, L[kx*2+1].x,
                                  L[kx*2+0].y, L[kx*2+1].y};
                #pragma unroll
                for (int r = 0; r < 4; r++) {
                    if (r > i || r < i - 2) continue;
                    const int kc = 3*(i - r) + kx;
                    uint2 f0 = sW3[(kc*4 + 0)*32 + lane];
                    uint2 f1 = sW3[(kc*4 + 1)*32 + lane];
                    uint2 f2 = sW3[(kc*4 + 2)*32 + lane];
                    uint2 f3 = sW3[(kc*4 + 3)*32 + lane];
                    mma16816h(acc[r][0], ah, f0.x, f0.y);
                    mma16816h(acc[r][1], ah, f1.x, f1.y);
                    mma16816h(acc[r][2], ah, f2.x, f2.y);
                    mma16816h(acc[r][3], ah, f3.x, f3.y);
                }
            }
        }

        const int gp0 = ox0 + p0l;
        const int gp1 = ox0 + p1l;
        #pragma unroll
        for (int r = 0; r < 4; r++) {
            const int oy = oy0 + r;
            if (oy >= H3) break;
            const size_t rowbase = (size_t)oy * H3;
            #pragma unroll
            for (int px = 0; px < 2; px++) {
                const int pp = px ? gp1 : gp0;
                float o[6];
                #pragma unroll
                for (int k = 0; k < 6; k++) o[k] = 0.f;
                #pragma unroll
                for (int cg = 0; cg < 4; cg++) {
                    #pragma unroll
                    for (int j = 0; j < 2; j++) {
                        const int ch = cg*8 + ci0 + j;
                        float t = acc[r][cg][px*2 + j] + sBA3[ch];
                        t = (t >= 0.f) ? t : sBA3[32+ch]*t;
                        o[0] = fmaf(t, sHW[0][ch], o[0]);
                        o[1] = fmaf(t, sHW[1][ch], o[1]);
                        o[2] = fmaf(t, sHW[2][ch], o[2]);
                        o[3] = fmaf(t, sHW[3][ch], o[3]);
                        o[4] = fmaf(t, sHW[4][ch], o[4]);
                        o[5] = fmaf(t, sHW[5][ch], o[5]);
                    }
                }
                #pragma unroll
                for (int off = 1; off <= 2; off <<= 1)
                    #pragma unroll
                    for (int k = 0; k < 6; k++)
                        o[k] += __shfl_xor_sync(0xffffffffu, o[k], off);

                float l0 = o[0] + sHB[0], l1 = o[1] + sHB[1];
                float m  = fmaxf(l0, l1);
                float e0 = expf(l0 - m), e1 = expf(l1 - m);
                float inv = 1.f / (e0 + e1);
                float pr0 = e0 * inv, pr1 = e1 * inv;

                if (pp < H3) {
                    const size_t p = rowbase + pp;
                    regp[(size_t)(b*4+q)*P3 + p] = o[2+q] + sHB[2+q];
                    if (q == 0) probp[(size_t)(b*2+0)*P3 + p] = pr0;
                    if (q == 1) probp[(size_t)(b*2+1)*P3 + p] = pr1;
                }
            }
        }
    }
}

// ---------------------------------------------------------------------------
extern "C" void kernel_launch(void* const* d_in, const int* in_sizes, int n_in,
                              void* d_out, int out_size)
{
    const float* x    = (const float*)d_in[0];
    const float* c1w  = (const float*)d_in[1];
    const float* c1b  = (const float*)d_in[2];
    const float* p1a  = (const float*)d_in[3];
    const float* c2w  = (const float*)d_in[4];
    const float* c2b  = (const float*)d_in[5];
    const float* p2a  = (const float*)d_in[6];
    const float* c3w  = (const float*)d_in[7];
    const float* c3b  = (const float*)d_in[8];
    const float* p3a  = (const float*)d_in[9];
    const float* c41w = (const float*)d_in[10];
    const float* c41b = (const float*)d_in[11];
    const float* c42w = (const float*)d_in[12];
    const float* c42b = (const float*)d_in[13];
    float* out = (float*)d_out;

    {
        dim3 blk(32, 4);
        dim3 grd((HP + 31) / 32, (HP + 3) / 4, B);
        k_conv1_pool<<<grd, blk>>>(x, c1w, c1b, p1a);
    }
    {
        dim3 grd((H3 + 127) / 128, (H3 + 3) / 4, B);
        k_conv23_fused<<<grd, 288>>>(c2w, c2b, p2a, c3w, c3b, p3a,
                                     c41w, c41b, c42w, c42b, out);
    }
}